// round 2
// baseline (speedup 1.0000x reference)
#include <cuda_runtime.h>
#include <cuda_bf16.h>
#include <mma.h>
#include <cstdint>

using namespace nvcuda;

#define BATCH   4
#define T_SEQ   64
#define NSPAT   196
#define CDIM    768
#define HEADS   12
#define HD      64
#define M_TOT   (BATCH * T_SEQ * NSPAT)   // 50176
#define QKV_N   (3 * CDIM)                // 2304

// Scratch (device globals: allocation-free per harness rules)
__device__ float g_qkv[(size_t)M_TOT * QKV_N];   // 462 MB
__device__ float g_att[(size_t)M_TOT * CDIM];    // 154 MB

// ---------------------------------------------------------------------------
// TF32 WMMA GEMM, 3-stage cp.async pipeline.
// C[m][n] = sum_k A[m*K+k] * B[n*K+k]  (+ optional bias[n])
// Block tile 128x128, BK=32. 256 threads = 8 warps in 2(m) x 4(n),
// warp tile 64x32 = 4x2 fragments of 16x16x8.
// ---------------------------------------------------------------------------
#define BM 128
#define BN 128
#define BK 32
#define STAGES 3
#define LDS_T 36                          // smem row stride (floats), 144B (16B aligned)
#define STAGE_F (128 * LDS_T)             // floats per stage per operand
#define LDC_S 132                         // epilogue staging stride (528B, 16B aligned)

__device__ __forceinline__ void cp_async16(uint32_t saddr, const void* gptr) {
    asm volatile("cp.async.cg.shared.global [%0], [%1], 16;\n" :: "r"(saddr), "l"(gptr));
}
__device__ __forceinline__ void cp_commit() {
    asm volatile("cp.async.commit_group;\n" ::: "memory");
}
__device__ __forceinline__ void cp_wait1() {
    asm volatile("cp.async.wait_group 1;\n" ::: "memory");
}

__global__ void __launch_bounds__(256) gemm_tf32_pipe_kernel(
    const float* __restrict__ A, const float* __restrict__ B,
    float* __restrict__ C, const float* __restrict__ bias,
    int M, int N, int K)
{
    extern __shared__ float smem[];
    float* As = smem;                        // STAGES * STAGE_F
    float* Bs = smem + STAGES * STAGE_F;     // STAGES * STAGE_F

    const int n0 = blockIdx.x * BN;          // N fastest -> weight resident in L2
    const int m0 = blockIdx.y * BM;

    const int tid  = threadIdx.x;
    const int warp = tid >> 5;
    const int wm   = warp >> 2;   // 0..1  -> rows wm*64
    const int wn   = warp & 3;    // 0..3  -> cols wn*32

    // per-thread cp.async source/dest mapping: 4 chunks for A, 4 for B per stage
    // id = tid + i*256 ; row = id>>3 (0..127), k4 = id&7 (8 float4 per row)
    const int ldrow = tid >> 3;
    const int ldk4  = tid & 7;

    wmma::fragment<wmma::accumulator, 16, 16, 8, float> acc[4][2];
    #pragma unroll
    for (int i = 0; i < 4; i++)
        #pragma unroll
        for (int j = 0; j < 2; j++)
            wmma::fill_fragment(acc[i][j], 0.0f);

    const int NB = K / BK;   // 24

    auto issue_stage = [&](int kb, int stg) {
        const float* Ag = A + (size_t)(m0 + ldrow) * K + kb * BK + ldk4 * 4;
        const float* Bg = B + (size_t)(n0 + ldrow) * K + kb * BK + ldk4 * 4;
        uint32_t sa = (uint32_t)__cvta_generic_to_shared(
            &As[stg * STAGE_F + ldrow * LDS_T + ldk4 * 4]);
        uint32_t sb = (uint32_t)__cvta_generic_to_shared(
            &Bs[stg * STAGE_F + ldrow * LDS_T + ldk4 * 4]);
        #pragma unroll
        for (int i = 0; i < 4; i++) {
            cp_async16(sa + i * 32 * LDS_T * 4, Ag + (size_t)(i * 32) * K);
            cp_async16(sb + i * 32 * LDS_T * 4, Bg + (size_t)(i * 32) * K);
        }
    };

    // prologue: stages 0..STAGES-2
    issue_stage(0, 0); cp_commit();
    issue_stage(1, 1); cp_commit();

    for (int kb = 0; kb < NB; kb++) {
        cp_wait1();            // stage kb resident (always 2 groups pending before this)
        __syncthreads();       // also protects buffer (kb+STAGES-1)%STAGES from overwrite

        // keep the pending-group invariant: commit every iteration (maybe empty)
        if (kb + STAGES - 1 < NB) issue_stage(kb + STAGES - 1, (kb + STAGES - 1) % STAGES);
        cp_commit();

        const float* a_st = &As[(kb % STAGES) * STAGE_F];
        const float* b_st = &Bs[(kb % STAGES) * STAGE_F];

        #pragma unroll
        for (int kk = 0; kk < BK; kk += 8) {
            wmma::fragment<wmma::matrix_a, 16, 16, 8, wmma::precision::tf32, wmma::row_major> af[4];
            wmma::fragment<wmma::matrix_b, 16, 16, 8, wmma::precision::tf32, wmma::col_major> bf[2];
            #pragma unroll
            for (int i = 0; i < 4; i++) {
                wmma::load_matrix_sync(af[i], &a_st[(wm * 64 + i * 16) * LDS_T + kk], LDS_T);
                #pragma unroll
                for (int t = 0; t < af[i].num_elements; t++)
                    af[i].x[t] = wmma::__float_to_tf32(af[i].x[t]);
            }
            #pragma unroll
            for (int j = 0; j < 2; j++) {
                wmma::load_matrix_sync(bf[j], &b_st[(wn * 32 + j * 16) * LDS_T + kk], LDS_T);
                #pragma unroll
                for (int t = 0; t < bf[j].num_elements; t++)
                    bf[j].x[t] = wmma::__float_to_tf32(bf[j].x[t]);
            }
            #pragma unroll
            for (int i = 0; i < 4; i++)
                #pragma unroll
                for (int j = 0; j < 2; j++)
                    wmma::mma_sync(acc[i][j], af[i], bf[j], acc[i][j]);
        }
        __syncthreads();
    }

    // ---- epilogue: stage through smem, fused bias, coalesced float4 stores ----
    float* sC = smem;   // 128 * LDC_S floats = 67.6KB, fits in pipeline smem
    #pragma unroll
    for (int i = 0; i < 4; i++)
        #pragma unroll
        for (int j = 0; j < 2; j++)
            wmma::store_matrix_sync(&sC[(wm * 64 + i * 16) * LDC_S + wn * 32 + j * 16],
                                    acc[i][j], LDC_S, wmma::mem_row_major);
    __syncthreads();

    #pragma unroll
    for (int it = 0; it < 16; it++) {
        int idx = tid + it * 256;         // 4096 float4 total
        int row = idx >> 5;               // 0..127
        int c4  = idx & 31;               // 0..31
        float4 v = *(float4*)&sC[row * LDC_S + c4 * 4];
        if (bias) {
            float4 bv = *(const float4*)&bias[n0 + c4 * 4];
            v.x += bv.x; v.y += bv.y; v.z += bv.z; v.w += bv.w;
        }
        *(float4*)&C[(size_t)(m0 + row) * N + n0 + c4 * 4] = v;
    }
}

// ---------------------------------------------------------------------------
// Causal attention per (b,h,n): T=64, hd=64. 256 threads, 4x4 per-thread tiles.
// ---------------------------------------------------------------------------
#define LDT 68   // transposed-tile row stride (floats); 272B, 16B aligned

__global__ void __launch_bounds__(256) attn_kernel(
    const float* __restrict__ qkv, float* __restrict__ att)
{
    extern __shared__ float smem[];
    float* sQ = smem;                 // [d][t] stride LDT
    float* sK = smem + 64 * LDT;      // [d][t] stride LDT
    float* sV = smem + 2 * 64 * LDT;  // [t][d] stride 64
    float* sP = sQ;                   // reused: [j][i] stride LDT

    const int blk = blockIdx.x;       // n + NSPAT*(h + HEADS*b)
    const int n = blk % NSPAT;
    const int h = (blk / NSPAT) % HEADS;
    const int b = blk / (NSPAT * HEADS);

    const int tid = threadIdx.x;
    const size_t rowstride = (size_t)NSPAT * QKV_N;
    const size_t base = ((size_t)b * T_SEQ * NSPAT + n) * QKV_N + (size_t)h * HD;

    for (int idx = tid; idx < 64 * 64; idx += 256) {
        int t = idx >> 6;
        int d = idx & 63;
        size_t g = base + (size_t)t * rowstride;
        sQ[d * LDT + t] = qkv[g + d];
        sK[d * LDT + t] = qkv[g + CDIM + d];
        sV[t * 64 + d]  = qkv[g + 2 * CDIM + d];
    }
    __syncthreads();

    const int ti = tid >> 4;  // rows 4*ti..4*ti+3
    const int tj = tid & 15;  // cols 4*tj..4*tj+3

    float accS[16];
    #pragma unroll
    for (int i = 0; i < 16; i++) accS[i] = 0.0f;

    #pragma unroll 4
    for (int d = 0; d < 64; d++) {
        float4 a4 = *(const float4*)&sQ[d * LDT + 4 * ti];
        float4 b4 = *(const float4*)&sK[d * LDT + 4 * tj];
        float av[4] = {a4.x, a4.y, a4.z, a4.w};
        float bv[4] = {b4.x, b4.y, b4.z, b4.w};
        #pragma unroll
        for (int ii = 0; ii < 4; ii++)
            #pragma unroll
            for (int jj = 0; jj < 4; jj++)
                accS[ii * 4 + jj] += av[ii] * bv[jj];
    }

    const float scale = 0.125f;   // hd^-0.5
    #pragma unroll
    for (int ii = 0; ii < 4; ii++) {
        int i = 4 * ti + ii;
        float mx = -3.402823466e38f;
        #pragma unroll
        for (int jj = 0; jj < 4; jj++) {
            int j = 4 * tj + jj;
            float s = (j <= i) ? accS[ii * 4 + jj] * scale : -3.402823466e38f;
            accS[ii * 4 + jj] = s;
            mx = fmaxf(mx, s);
        }
        #pragma unroll
        for (int m = 8; m >= 1; m >>= 1)
            mx = fmaxf(mx, __shfl_xor_sync(0xffffffffu, mx, m));
        float sum = 0.0f;
        #pragma unroll
        for (int jj = 0; jj < 4; jj++) {
            float e = __expf(accS[ii * 4 + jj] - mx);
            accS[ii * 4 + jj] = e;
            sum += e;
        }
        #pragma unroll
        for (int m = 8; m >= 1; m >>= 1)
            sum += __shfl_xor_sync(0xffffffffu, sum, m);
        float inv = 1.0f / sum;
        #pragma unroll
        for (int jj = 0; jj < 4; jj++) accS[ii * 4 + jj] *= inv;
    }

    __syncthreads();
    #pragma unroll
    for (int ii = 0; ii < 4; ii++)
        #pragma unroll
        for (int jj = 0; jj < 4; jj++)
            sP[(4 * tj + jj) * LDT + 4 * ti + ii] = accS[ii * 4 + jj];
    __syncthreads();

    float o[16];
    #pragma unroll
    for (int i = 0; i < 16; i++) o[i] = 0.0f;

    #pragma unroll 4
    for (int j = 0; j < 64; j++) {
        float4 p4 = *(const float4*)&sP[j * LDT + 4 * ti];
        float4 v4 = *(const float4*)&sV[j * 64 + 4 * tj];
        float pv[4] = {p4.x, p4.y, p4.z, p4.w};
        float vv[4] = {v4.x, v4.y, v4.z, v4.w};
        #pragma unroll
        for (int ii = 0; ii < 4; ii++)
            #pragma unroll
            for (int jj = 0; jj < 4; jj++)
                o[ii * 4 + jj] += pv[ii] * vv[jj];
    }

    #pragma unroll
    for (int ii = 0; ii < 4; ii++) {
        int i = 4 * ti + ii;
        size_t addr = (((size_t)b * T_SEQ + i) * NSPAT + n) * CDIM + (size_t)h * HD + 4 * tj;
        float4 o4 = make_float4(o[ii * 4 + 0], o[ii * 4 + 1], o[ii * 4 + 2], o[ii * 4 + 3]);
        *(float4*)&att[addr] = o4;
    }
}

// ---------------------------------------------------------------------------
extern "C" void kernel_launch(void* const* d_in, const int* in_sizes, int n_in,
                              void* d_out, int out_size)
{
    const float* x      = (const float*)d_in[0];
    const float* w_qkv  = (const float*)d_in[1];
    const float* w_proj = (const float*)d_in[2];
    const float* b_proj = (const float*)d_in[3];
    float* out = (float*)d_out;

    float* qkv_buf = nullptr;
    float* att_buf = nullptr;
    cudaGetSymbolAddress((void**)&qkv_buf, g_qkv);
    cudaGetSymbolAddress((void**)&att_buf, g_att);

    const int gemm_smem = STAGES * STAGE_F * 2 * 4;        // 110,592 B
    const int attn_smem = 2 * 64 * LDT * 4 + 64 * 64 * 4;  // 51,200 B
    static bool attr_done = false;
    if (!attr_done) {
        cudaFuncSetAttribute(gemm_tf32_pipe_kernel,
                             cudaFuncAttributeMaxDynamicSharedMemorySize, gemm_smem);
        cudaFuncSetAttribute(attn_kernel,
                             cudaFuncAttributeMaxDynamicSharedMemorySize, attn_smem);
        attr_done = true;
    }

    // 1) QKV GEMM: (50176 x 768) @ (2304 x 768)^T
    {
        dim3 grid(QKV_N / BN, M_TOT / BM);   // (18, 392)
        gemm_tf32_pipe_kernel<<<grid, 256, gemm_smem>>>(
            x, w_qkv, qkv_buf, nullptr, M_TOT, QKV_N, CDIM);
    }
    // 2) Attention: one block per (b,h,n)
    {
        dim3 grid(BATCH * HEADS * NSPAT);    // 9408
        attn_kernel<<<grid, 256, attn_smem>>>(qkv_buf, att_buf);
    }
    // 3) Projection GEMM + fused bias: (50176 x 768) @ (768 x 768)^T -> d_out
    {
        dim3 grid(CDIM / BN, M_TOT / BM);    // (6, 392)
        gemm_tf32_pipe_kernel<<<grid, 256, gemm_smem>>>(
            att_buf, w_proj, out, b_proj, M_TOT, CDIM, CDIM);
    }
}